// round 1
// baseline (speedup 1.0000x reference)
#include <cuda_runtime.h>
#include <cstdint>
#include <math.h>

// Problem constants (DemoGuidedStudent): x [256,4096] int32 in {0..5}
#define BB   256
#define SS   4096
#define VV   6
#define DD   32
#define HH   16
#define PADV 5
#define KK   614   // max(1, int(4096*0.15))

// Fused kernel: one block per batch row.
//  Stage A: load x row -> shared (packed bytes); compute per-vocab table,
//           selector scores, approximator rows (tiny MLPs, L2-hot weights).
//  Stage B: emit scores[b,:] = score_table[x]; per-chunk vocab counts packed
//           into 6x10-bit fields of a u64, warp shuffle scan + cross-warp scan
//           -> stable per-vocab exclusive ordinals.
//  Stage C: rank vocab by descending score; per-vocab take/base from budget;
//           emit top_idx (stable, matches jax.lax.top_k tie order).
//  Stage D: pooled = sum_v take[v]*a_row[v]/K; classifier MLP -> pred[b].
__global__ __launch_bounds__(256, 4) void fused_row_kernel(
    const int*   __restrict__ x,
    const float* __restrict__ emb,
    const float* __restrict__ sw1, const float* __restrict__ sb1,
    const float* __restrict__ sw2, const float* __restrict__ sb2,
    const float* __restrict__ aw1, const float* __restrict__ ab1,
    const float* __restrict__ aw2, const float* __restrict__ ab2,
    const float* __restrict__ cw1, const float* __restrict__ cb1,
    const float* __restrict__ cw2, const float* __restrict__ cb2,
    float* __restrict__ out_pred,
    float* __restrict__ out_top,
    float* __restrict__ out_sc)
{
    __shared__ float    table[VV][DD];
    __shared__ float    rbuf[VV][DD];
    __shared__ float    hbuf[VV][HH];
    __shared__ float    arow[VV][DD];
    __shared__ float    sscore[VV];
    __shared__ int      srank[VV];
    __shared__ uint32_t tok_u32[SS / 4];   // 4 tokens packed per u32
    __shared__ int      warpsum[8][VV];
    __shared__ int      ctotal[VV];
    __shared__ int      take[VV], obase[VV];
    __shared__ float    pooled[DD];
    __shared__ float    h2[HH];

    const int t    = threadIdx.x;
    const int b    = blockIdx.x;
    const int lane = t & 31;
    const int warp = t >> 5;

    // ---- Stage A0: issue global loads of the x row early (coalesced int4) ----
    const int4* xr = (const int4*)(x + b * SS);
    int4 xw[4];
    #pragma unroll
    for (int it = 0; it < 4; ++it) xw[it] = xr[t + it * 256];

    // table = emb with PAD row zeroed
    if (t < VV * DD) {
        int v = t >> 5, i = t & 31;
        table[v][i] = (v == PADV) ? 0.0f : emb[v * DD + i];
    }
    // pack tokens as bytes into shared
    #pragma unroll
    for (int it = 0; it < 4; ++it) {
        int4 w = xw[it];
        tok_u32[t + it * 256] = (uint32_t)w.x | ((uint32_t)w.y << 8) |
                                ((uint32_t)w.z << 16) | ((uint32_t)w.w << 24);
    }
    __syncthreads();

    // ---- Stage A1: hidden layers of selector + approximator ----
    if (t < VV * DD) {                       // approximator hidden: relu(table@aw1+ab1)
        int v = t >> 5, i = t & 31;
        float acc = ab1[i];
        #pragma unroll
        for (int d = 0; d < DD; ++d) acc += table[v][d] * aw1[d * DD + i];
        rbuf[v][i] = fmaxf(acc, 0.0f);
    }
    if (t < VV * HH) {                       // selector hidden: relu(table@sw1+sb1)
        int v = t >> 4, j = t & 15;
        float acc = sb1[j];
        #pragma unroll
        for (int d = 0; d < DD; ++d) acc += table[v][d] * sw1[d * HH + j];
        hbuf[v][j] = fmaxf(acc, 0.0f);
    }
    __syncthreads();

    // ---- Stage A2: scores per vocab + approximator output rows ----
    if (t < VV * DD) {                       // a_row = rbuf@aw2 + ab2
        int v = t >> 5, i = t & 31;
        float acc = ab2[i];
        #pragma unroll
        for (int m = 0; m < DD; ++m) acc += rbuf[v][m] * aw2[m * DD + i];
        arow[v][i] = acc;
    }
    if (t >= 224 && t < 224 + VV) {          // score = sigmoid(hbuf@sw2 + sb2)
        int v = t - 224;
        float acc = sb2[0];
        #pragma unroll
        for (int j = 0; j < HH; ++j) acc += hbuf[v][j] * sw2[j];
        sscore[v] = 1.0f / (1.0f + expf(-acc));
    }
    __syncthreads();

    // ---- Stage B: counts (packed u64, 10 bits per vocab) + scores output ----
    uint4 chunk = ((const uint4*)tok_u32)[t];        // bytes 16t .. 16t+15
    uint32_t cw[4] = {chunk.x, chunk.y, chunk.z, chunk.w};
    unsigned long long cpack = 0ull;
    #pragma unroll
    for (int q = 0; q < 4; ++q)
        #pragma unroll
        for (int j = 0; j < 4; ++j) {
            int v = (cw[q] >> (8 * j)) & 0xFF;
            cpack += 1ull << (10 * v);
        }
    unsigned long long own = cpack;
    // warp-level inclusive scan of packed counts
    #pragma unroll
    for (int off = 1; off < 32; off <<= 1) {
        unsigned long long n = __shfl_up_sync(0xffffffffu, cpack, off);
        if (lane >= off) cpack += n;
    }
    if (lane == 31) {
        #pragma unroll
        for (int v = 0; v < VV; ++v)
            warpsum[warp][v] = (int)((cpack >> (10 * v)) & 1023ull);
    }
    if (t == 0) {
        // stable selection sort of 6 scores, descending (ties: lower vocab first)
        int   order[VV];
        float sc[VV];
        #pragma unroll
        for (int v = 0; v < VV; ++v) { order[v] = v; sc[v] = sscore[v]; }
        for (int a = 0; a < VV; ++a) {
            int best = a;
            for (int c = a + 1; c < VV; ++c)
                if (sc[order[c]] > sc[order[best]]) best = c;
            int tmp = order[a]; order[a] = order[best]; order[best] = tmp;
        }
        #pragma unroll
        for (int a = 0; a < VV; ++a) srank[a] = order[a];
    }
    // emit scores row (coalesced float4 stores)
    {
        float* srow = out_sc + (size_t)b * SS;
        #pragma unroll
        for (int it = 0; it < 4; ++it) {
            uint32_t w = tok_u32[t + it * 256];
            float4 f;
            f.x = sscore[w & 0xFF];
            f.y = sscore[(w >> 8) & 0xFF];
            f.z = sscore[(w >> 16) & 0xFF];
            f.w = sscore[(w >> 24) & 0xFF];
            ((float4*)srow)[t + it * 256] = f;
        }
    }
    __syncthreads();

    // ---- cross-warp exclusive scan of per-vocab warp totals ----
    if (t < VV) {
        int run = 0;
        #pragma unroll
        for (int w = 0; w < 8; ++w) { int s = warpsum[w][t]; warpsum[w][t] = run; run += s; }
        ctotal[t] = run;
    }
    __syncthreads();

    // ---- Stage C0: per-vocab take counts and output bases from the budget ----
    if (t == 0) {
        int budget = KK, off = 0;
        #pragma unroll
        for (int r = 0; r < VV; ++r) {
            int v  = srank[r];
            int tk = min(ctotal[v], budget);
            take[v]  = tk;
            obase[v] = off;
            off    += tk;
            budget -= tk;
        }
    }
    __syncthreads();

    // ---- Stage C1: emit top_idx (stable within vocab, vocab in score order) ----
    {
        unsigned long long excl = cpack - own;   // exclusive prefix within warp
        int o[VV];
        #pragma unroll
        for (int v = 0; v < VV; ++v)
            o[v] = warpsum[warp][v] + (int)((excl >> (10 * v)) & 1023ull);

        float* trow = out_top + (size_t)b * KK;
        #pragma unroll
        for (int q = 0; q < 4; ++q)
            #pragma unroll
            for (int j = 0; j < 4; ++j) {
                int v   = (cw[q] >> (8 * j)) & 0xFF;
                int ord = o[v]++;
                if (ord < take[v])
                    trow[obase[v] + ord] = (float)(t * 16 + q * 4 + j);
            }
    }

    // ---- Stage D: pooled mean + classifier ----
    if (t < DD) {
        float acc = 0.0f;
        #pragma unroll
        for (int v = 0; v < VV; ++v) acc += (float)take[v] * arow[v][t];
        pooled[t] = acc * (1.0f / (float)KK);
    }
    __syncthreads();
    if (t < HH) {
        float acc = cb1[t];
        #pragma unroll
        for (int d = 0; d < DD; ++d) acc += pooled[d] * cw1[d * HH + t];
        h2[t] = fmaxf(acc, 0.0f);
    }
    __syncthreads();
    if (t == 0) {
        float acc = cb2[0];
        #pragma unroll
        for (int j = 0; j < HH; ++j) acc += h2[j] * cw2[j];
        out_pred[b] = 1.0f / (1.0f + expf(-acc));
    }
}

extern "C" void kernel_launch(void* const* d_in, const int* in_sizes, int n_in,
                              void* d_out, int out_size) {
    const int*   x   = (const int*)  d_in[0];
    const float* emb = (const float*)d_in[1];
    const float* sw1 = (const float*)d_in[2];
    const float* sb1 = (const float*)d_in[3];
    const float* sw2 = (const float*)d_in[4];
    const float* sb2 = (const float*)d_in[5];
    const float* aw1 = (const float*)d_in[6];
    const float* ab1 = (const float*)d_in[7];
    const float* aw2 = (const float*)d_in[8];
    const float* ab2 = (const float*)d_in[9];
    const float* cw1 = (const float*)d_in[10];
    const float* cb1 = (const float*)d_in[11];
    const float* cw2 = (const float*)d_in[12];
    const float* cb2 = (const float*)d_in[13];

    // Output: concat of flattened (pred [B], top_idx [B,K], scores [B,S]) as f32
    float* out      = (float*)d_out;
    float* out_pred = out;
    float* out_top  = out + BB;
    float* out_sc   = out + BB + (size_t)BB * KK;

    fused_row_kernel<<<BB, 256>>>(x, emb, sw1, sb1, sw2, sb2,
                                  aw1, ab1, aw2, ab2,
                                  cw1, cb1, cw2, cb2,
                                  out_pred, out_top, out_sc);
}